// round 2
// baseline (speedup 1.0000x reference)
#include <cuda_runtime.h>
#include <math.h>

#define NQ   4096
#define NKV  32768
#define CDIM 256
#define KSEL 100
#define CCAP 1024

__device__ int g_topk[NQ * KSEL];

// ---------------------------------------------------------------------------
// Kernel 1: per-query exact top-100 nearest neighbors (by squared distance,
// monotone-equivalent to the reference's sqrt distance), smallest-index
// tie-break to match jax.lax.top_k stability.
// One CTA (256 threads) per query. All 32768 d^2 bit patterns live in smem.
// ---------------------------------------------------------------------------
__global__ void __launch_bounds__(256, 1)
select_kernel(const float* __restrict__ q_pos, const float* __restrict__ k_pos)
{
    extern __shared__ unsigned smem_u[];
    unsigned* sbits    = smem_u;             // 32768  d^2 bit patterns
    unsigned* hist     = sbits + NKV;        // 16*256 per-thread histogram rows
    unsigned* binTotal = hist + 16 * 256;    // 16
    unsigned* ctrl     = binTotal + 16;      // 8 control words
    unsigned* cbits    = ctrl + 8;           // CCAP compacted candidates
    unsigned* tieIdx   = cbits + CCAP;       // 256 tie indices
    unsigned* scnt     = tieIdx + 256;       // 256 (scan scratch, unused slots ok)
    unsigned* wtot     = scnt + 256;         // 8 warp totals

    const int tid = threadIdx.x;
    const int q   = blockIdx.x;

    const float q0 = q_pos[3*q+0], q1 = q_pos[3*q+1], q2 = q_pos[3*q+2];
    const float sq = q0*q0 + q1*q1 + q2*q2;

    // ---- distance pass: 3x LDG.128 per 4 keys, store bits as uint4 ----
    const float4* kp4 = (const float4*)k_pos;
    for (int g = tid; g < NKV/4; g += 256) {
        float4 A = kp4[3*g+0];
        float4 B = kp4[3*g+1];
        float4 C = kp4[3*g+2];
        float kx[4] = {A.x, A.w, B.z, C.y};
        float ky[4] = {A.y, B.x, B.w, C.z};
        float kz[4] = {A.z, B.y, C.x, C.w};
        unsigned r[4];
        #pragma unroll
        for (int m = 0; m < 4; m++) {
            float dot = kx[m]*q0 + ky[m]*q1 + kz[m]*q2;
            float sk  = kx[m]*kx[m] + ky[m]*ky[m] + kz[m]*kz[m];
            float d2  = sq + sk - 2.0f*dot;   // same expansion as reference
            d2 = fmaxf(d2, 0.0f);             // non-negative -> bits monotone
            r[m] = __float_as_uint(d2);
        }
        ((uint4*)sbits)[g] = make_uint4(r[0], r[1], r[2], r[3]);
    }
    __syncthreads();

    // ---- 8-pass 4-bit radix select for the exact K-th smallest value ----
    unsigned prefix = 0;
    int kneed = KSEL;     // rank needed inside current candidate set
    int curN  = -1;       // -1: candidates implicit (full array); else compact count

    for (int pass = 0; pass < 8; pass++) {
        const int shift = 28 - 4*pass;
        #pragma unroll
        for (int b = 0; b < 16; b++) hist[b*256 + tid] = 0;
        __syncthreads();

        if (curN < 0) {
            for (int j = tid; j < NKV; j += 256) {
                unsigned u = sbits[j];
                bool ok = (pass == 0) || ((u >> (shift+4)) == prefix);
                if (ok) { unsigned b = (u >> shift) & 15u; hist[b*256 + tid]++; }
            }
        } else {
            for (int j = tid; j < curN; j += 256) {
                unsigned u = cbits[j];
                if ((u >> (shift+4)) == prefix) {
                    unsigned b = (u >> shift) & 15u; hist[b*256 + tid]++;
                }
            }
        }
        __syncthreads();

        // reduce 256 rows -> 16 bin totals (half-warp per bin)
        {
            int w = tid >> 5, lane = tid & 31;
            int bin = 2*w + (lane >> 4);
            int l16 = lane & 15;
            unsigned s = 0;
            #pragma unroll
            for (int i = 0; i < 16; i++) s += hist[bin*256 + l16 + 16*i];
            s += __shfl_xor_sync(0xFFFFFFFFu, s, 8);
            s += __shfl_xor_sync(0xFFFFFFFFu, s, 4);
            s += __shfl_xor_sync(0xFFFFFFFFu, s, 2);
            s += __shfl_xor_sync(0xFFFFFFFFu, s, 1);
            if (l16 == 0) binTotal[bin] = s;
        }
        __syncthreads();

        if (tid == 0) {
            unsigned cum = 0, cnt = 0; int b = 0;
            for (b = 0; b < 16; b++) {
                cnt = binTotal[b];
                if (cum + cnt >= (unsigned)kneed) break;
                cum += cnt;
            }
            ctrl[0] = (prefix << 4) | (unsigned)b;
            ctrl[1] = (unsigned)kneed - cum;
            ctrl[3] = cnt;
        }
        __syncthreads();
        prefix = ctrl[0];
        kneed  = (int)ctrl[1];
        unsigned cnt = ctrl[3];
        __syncthreads();

        // compact surviving candidates once they fit (order-independent use)
        if (curN < 0 && cnt <= CCAP && pass < 7) {
            if (tid == 0) ctrl[2] = 0;
            __syncthreads();
            for (int j = tid; j < NKV; j += 256) {
                unsigned u = sbits[j];
                if ((u >> shift) == prefix) {
                    unsigned p = atomicAdd(&ctrl[2], 1u);
                    if (p < CCAP) cbits[p] = u;
                }
            }
            __syncthreads();
            curN = (int)min(ctrl[2], (unsigned)CCAP);
        }
    }

    // prefix == bits of K-th smallest value T; kneed == # ties still needed
    const unsigned T = prefix;

    // ---- deterministic collection of strictly-smaller indices (prefix scan) ----
    int myc = 0;
    for (int j = tid; j < NKV; j += 256) myc += (sbits[j] < T) ? 1 : 0;
    scnt[tid] = (unsigned)myc;
    if (tid == 0) ctrl[5] = 0;
    __syncthreads();

    {
        int lane = tid & 31, w = tid >> 5;
        unsigned v = scnt[tid];
        unsigned inc = v;
        #pragma unroll
        for (int o = 1; o < 32; o <<= 1) {
            unsigned t = __shfl_up_sync(0xFFFFFFFFu, inc, o);
            if (lane >= o) inc += t;
        }
        if (lane == 31) wtot[w] = inc;
        __syncthreads();
        if (tid < 8) {
            unsigned t = wtot[tid];
            unsigned i2 = t;
            #pragma unroll
            for (int o = 1; o < 8; o <<= 1) {
                unsigned x = __shfl_up_sync(0xFFu, i2, o);
                if (tid >= o) i2 += x;
            }
            wtot[tid] = i2 - t;   // exclusive warp offset
        }
        __syncthreads();
        unsigned off = inc - v + wtot[w];   // exclusive position of this thread
        const int base = q * KSEL;
        for (int j = tid; j < NKV; j += 256) {
            unsigned u = sbits[j];
            if (u < T) {
                g_topk[base + off] = j;
                off++;
            } else if (u == T) {
                unsigned p = atomicAdd(&ctrl[5], 1u);
                if (p < 256) tieIdx[p] = j;
            }
        }
    }
    __syncthreads();

    if (tid == 0) {
        int nLess  = KSEL - kneed;
        int tcount = min((int)ctrl[5], 256);
        unsigned last = 0;
        for (int r = 0; r < kneed; r++) {       // smallest-index ties first
            unsigned best = 0xFFFFFFFFu;
            for (int t = 0; t < tcount; t++) {
                unsigned v = tieIdx[t];
                bool gt = (r == 0) ? true : (v > last);
                if (gt && v < best) best = v;
            }
            g_topk[q*KSEL + nLess + r] = (int)best;
            last = best;
        }
    }
}

// ---------------------------------------------------------------------------
// Kernel 2: gathered attention + residual(=2x) + LayerNorm.
// One CTA (256 threads) per query; thread == output channel for PV/LN.
// ---------------------------------------------------------------------------
__global__ void __launch_bounds__(256)
attend_kernel(const float* __restrict__ q_feat, const float* __restrict__ k_feat,
              const float* __restrict__ v_feat, const float* __restrict__ gamma,
              const float* __restrict__ beta, float* __restrict__ out)
{
    __shared__ float qs[CDIM];
    __shared__ int   ids[KSEL];
    __shared__ float lg[KSEL];
    __shared__ float red[8];

    const int tid  = threadIdx.x;
    const int q    = blockIdx.x;
    const int w    = tid >> 5, lane = tid & 31;

    qs[tid] = q_feat[q*CDIM + tid];
    if (tid < KSEL) ids[tid] = g_topk[q*KSEL + tid];
    __syncthreads();

    // logits: one warp per neighbor (round-robin), coalesced 1KB k rows (L2 hit)
    for (int n = w; n < KSEL; n += 8) {
        const float* kr = k_feat + (size_t)ids[n] * CDIM;
        float p = 0.f;
        #pragma unroll
        for (int t = 0; t < 8; t++) p = fmaf(qs[lane + 32*t], kr[lane + 32*t], p);
        #pragma unroll
        for (int o = 16; o; o >>= 1) p += __shfl_xor_sync(0xFFFFFFFFu, p, o);
        if (lane == 0) lg[n] = p * 0.0625f;   // * C^{-1/2}
    }
    __syncthreads();

    // softmax over 100 logits, done by warp 0
    if (w == 0) {
        float v0 = lg[lane];
        float v1 = lg[lane + 32];
        float v2 = lg[lane + 64];                       // 64..95 all valid
        float v3 = (lane < 4) ? lg[lane + 96] : -INFINITY;
        float m = fmaxf(fmaxf(v0, v1), fmaxf(v2, v3));
        #pragma unroll
        for (int o = 16; o; o >>= 1) m = fmaxf(m, __shfl_xor_sync(0xFFFFFFFFu, m, o));
        float e0 = expf(v0 - m), e1 = expf(v1 - m), e2 = expf(v2 - m);
        float e3 = (lane < 4) ? expf(v3 - m) : 0.f;
        float s = e0 + e1 + e2 + e3;
        #pragma unroll
        for (int o = 16; o; o >>= 1) s += __shfl_xor_sync(0xFFFFFFFFu, s, o);
        float inv = 1.0f / s;
        lg[lane]       = e0 * inv;
        lg[lane + 32]  = e1 * inv;
        lg[lane + 64]  = e2 * inv;
        if (lane < 4) lg[lane + 96] = e3 * inv;
    }
    __syncthreads();

    // PV: thread owns one channel; 4 accumulators for ILP; coalesced v rows
    float a0 = 0.f, a1 = 0.f, a2 = 0.f, a3 = 0.f;
    for (int n = 0; n < KSEL; n += 4) {
        a0 = fmaf(lg[n+0], v_feat[(size_t)ids[n+0]*CDIM + tid], a0);
        a1 = fmaf(lg[n+1], v_feat[(size_t)ids[n+1]*CDIM + tid], a1);
        a2 = fmaf(lg[n+2], v_feat[(size_t)ids[n+2]*CDIM + tid], a2);
        a3 = fmaf(lg[n+3], v_feat[(size_t)ids[n+3]*CDIM + tid], a3);
    }
    float y = 2.0f * ((a0 + a1) + (a2 + a3));   // res row == x  ->  y = 2x

    // LayerNorm over 256 channels
    float s = y;
    #pragma unroll
    for (int o = 16; o; o >>= 1) s += __shfl_xor_sync(0xFFFFFFFFu, s, o);
    if (lane == 0) red[w] = s;
    __syncthreads();
    float tot = 0.f;
    #pragma unroll
    for (int i = 0; i < 8; i++) tot += red[i];
    float mean = tot * (1.0f / CDIM);
    float d = y - mean;
    float s2 = d * d;
    __syncthreads();
    #pragma unroll
    for (int o = 16; o; o >>= 1) s2 += __shfl_xor_sync(0xFFFFFFFFu, s2, o);
    if (lane == 0) red[w] = s2;
    __syncthreads();
    float tot2 = 0.f;
    #pragma unroll
    for (int i = 0; i < 8; i++) tot2 += red[i];
    float var = tot2 * (1.0f / CDIM);

    out[q*CDIM + tid] = d * rsqrtf(var + 1e-5f) * gamma[tid] + beta[tid];
}

// ---------------------------------------------------------------------------
extern "C" void kernel_launch(void* const* d_in, const int* in_sizes, int n_in,
                              void* d_out, int out_size)
{
    const float* q_feat = (const float*)d_in[1];
    const float* k_feat = (const float*)d_in[2];
    const float* v_feat = (const float*)d_in[3];
    const float* q_pos  = (const float*)d_in[4];
    const float* k_pos  = (const float*)d_in[5];
    const float* gamma  = (const float*)d_in[6];
    const float* beta   = (const float*)d_in[7];
    float* out = (float*)d_out;

    size_t smem = (size_t)(NKV + 16*256 + 16 + 8 + CCAP + 256 + 256 + 8) * sizeof(unsigned);
    cudaFuncSetAttribute(select_kernel,
                         cudaFuncAttributeMaxDynamicSharedMemorySize, (int)smem);

    select_kernel<<<NQ, 256, smem>>>(q_pos, k_pos);
    attend_kernel<<<NQ, 256>>>(q_feat, k_feat, v_feat, gamma, beta, out);
}

// round 7
// speedup vs baseline: 1.8242x; 1.8242x over previous
#include <cuda_runtime.h>
#include <math.h>

#define NQ   4096
#define NKV  32768
#define CDIM 256
#define KSEL 100
#define CCAP 1024
#define TCAP 1024

__device__ int g_topk[NQ * KSEL];

// Identical arithmetic in the distance pass and the tie-recompute path.
__device__ __forceinline__ unsigned d2bits(float q0, float q1, float q2, float sq,
                                           float kx, float ky, float kz)
{
    float dot = kx*q0 + ky*q1 + kz*q2;
    float sk  = kx*kx + ky*ky + kz*kz;
    float d2  = sq + sk - 2.0f*dot;      // same expansion as reference
    return __float_as_uint(fmaxf(d2, 0.0f));
}

// ---------------------------------------------------------------------------
// Kernel 1: exact top-100 NN per query via 16-bit-key radix select in smem.
//   - keys = top 16 bits of fp32 d^2 (monotone truncation)
//   - 4x 4-bit radix passes, pass 0 fused into the distance pass
//   - boundary (hi16 == T) candidates re-ranked at full fp32 precision + idx
// One CTA (256 thr) per query; 95KB smem -> 2 CTAs/SM.
// ---------------------------------------------------------------------------
__global__ void __launch_bounds__(256, 2)
select_kernel(const float* __restrict__ q_pos, const float* __restrict__ k_pos)
{
    extern __shared__ unsigned smem_u[];
    unsigned* keysU    = smem_u;              // NKV/2 words: packed ushort keys
    unsigned* hist     = keysU + NKV/2;       // 16*256 per-thread histogram rows
    unsigned* binTotal = hist + 16*256;       // 16
    unsigned* ctrl     = binTotal + 16;       // 8
    unsigned* cbits    = ctrl + 8;            // CCAP compacted keys
    unsigned* candI    = cbits + CCAP;        // TCAP tie indices
    unsigned* candD    = candI + TCAP;        // TCAP tie full d2 bits
    unsigned* scnt     = candD + TCAP;        // 256 scan scratch
    unsigned* wtot     = scnt + 256;          // 8 warp totals

    const int tid  = threadIdx.x;
    const int lane = tid & 31;
    const int q    = blockIdx.x;

    const float q0 = q_pos[3*q+0], q1 = q_pos[3*q+1], q2 = q_pos[3*q+2];
    const float sq = q0*q0 + q1*q1 + q2*q2;

    // zero pass-0 histogram (per-thread rows: no barrier needed before use)
    #pragma unroll
    for (int b = 0; b < 16; b++) hist[b*256 + tid] = 0;

    // ---- distance pass (fused pass-0 histogram on top 4 key bits) ----
    const float4* kp4 = (const float4*)k_pos;
    for (int g = tid; g < NKV/4; g += 256) {
        float4 A = kp4[3*g+0];
        float4 B = kp4[3*g+1];
        float4 C = kp4[3*g+2];
        float kx[4] = {A.x, A.w, B.z, C.y};
        float ky[4] = {A.y, B.x, B.w, C.z};
        float kz[4] = {A.z, B.y, C.x, C.w};
        unsigned k16[4];
        #pragma unroll
        for (int m = 0; m < 4; m++) {
            unsigned key = d2bits(q0, q1, q2, sq, kx[m], ky[m], kz[m]) >> 16;
            hist[(key >> 12)*256 + tid]++;
            k16[m] = key;
        }
        ((uint2*)keysU)[g] = make_uint2(k16[0] | (k16[1] << 16),
                                        k16[2] | (k16[3] << 16));
    }

    // ---- 4-pass 4-bit radix select over 16-bit keys ----
    unsigned prefix = 0;
    int kneed = KSEL;
    int curN  = -1;      // -1: full array is the candidate scope

    for (int p = 0; p < 4; p++) {
        const int shift = 12 - 4*p;
        if (p > 0) {
            #pragma unroll
            for (int b = 0; b < 16; b++) hist[b*256 + tid] = 0;
            if (curN < 0) {
                for (int j = tid; j < NKV/2; j += 256) {
                    unsigned w  = keysU[j];
                    unsigned k0 = w & 0xFFFFu, k1 = w >> 16;
                    if ((k0 >> (shift+4)) == prefix) hist[((k0 >> shift) & 15u)*256 + tid]++;
                    if ((k1 >> (shift+4)) == prefix) hist[((k1 >> shift) & 15u)*256 + tid]++;
                }
            } else {
                for (int j = tid; j < curN; j += 256) {
                    unsigned k = cbits[j];
                    if ((k >> (shift+4)) == prefix) hist[((k >> shift) & 15u)*256 + tid]++;
                }
            }
        }
        __syncthreads();

        // reduce 256 rows -> 16 totals (half-warp per bin)
        {
            int w = tid >> 5, bin = 2*w + (lane >> 4), l16 = lane & 15;
            unsigned s = 0;
            #pragma unroll
            for (int i = 0; i < 16; i++) s += hist[bin*256 + l16 + 16*i];
            s += __shfl_xor_sync(0xFFFFFFFFu, s, 8);
            s += __shfl_xor_sync(0xFFFFFFFFu, s, 4);
            s += __shfl_xor_sync(0xFFFFFFFFu, s, 2);
            s += __shfl_xor_sync(0xFFFFFFFFu, s, 1);
            if (l16 == 0) binTotal[bin] = s;
        }
        __syncthreads();

        if (tid == 0) {
            unsigned cum = 0, cnt = 0; int b = 0;
            for (b = 0; b < 16; b++) {
                cnt = binTotal[b];
                if (cum + cnt >= (unsigned)kneed) break;
                cum += cnt;
            }
            ctrl[0] = (prefix << 4) | (unsigned)b;
            ctrl[1] = (unsigned)kneed - cum;
            ctrl[3] = cnt;
            ctrl[5] = 0;
        }
        __syncthreads();
        prefix = ctrl[0];
        kneed  = (int)ctrl[1];
        unsigned cnt = ctrl[3];
        __syncthreads();

        // compact surviving scope when it fits (warp-aggregated append)
        if (curN < 0 && cnt <= CCAP && p < 3) {
            if (tid == 0) ctrl[2] = 0;
            __syncthreads();
            for (int j = tid; j < NKV/2; j += 256) {
                unsigned w  = keysU[j];
                unsigned k0 = w & 0xFFFFu, k1 = w >> 16;
                bool p0 = ((k0 >> shift) == prefix);
                bool p1 = ((k1 >> shift) == prefix);
                unsigned m0 = __ballot_sync(0xFFFFFFFFu, p0);
                if (m0) {
                    int ld = __ffs(m0) - 1; unsigned base = 0;
                    if (lane == ld) base = atomicAdd(&ctrl[2], (unsigned)__popc(m0));
                    base = __shfl_sync(0xFFFFFFFFu, base, ld);
                    if (p0) {
                        unsigned pos = base + __popc(m0 & ((1u << lane) - 1));
                        if (pos < CCAP) cbits[pos] = k0;
                    }
                }
                unsigned m1 = __ballot_sync(0xFFFFFFFFu, p1);
                if (m1) {
                    int ld = __ffs(m1) - 1; unsigned base = 0;
                    if (lane == ld) base = atomicAdd(&ctrl[2], (unsigned)__popc(m1));
                    base = __shfl_sync(0xFFFFFFFFu, base, ld);
                    if (p1) {
                        unsigned pos = base + __popc(m1 & ((1u << lane) - 1));
                        if (pos < CCAP) cbits[pos] = k1;
                    }
                }
            }
            __syncthreads();
            curN = (int)min(ctrl[2], (unsigned)CCAP);
        }
    }

    const unsigned T = prefix;          // 16-bit key of the 100th element
    const int base = q * KSEL;

    // ---- count strictly-smaller keys per thread ----
    int myc = 0;
    for (int j = tid; j < NKV/2; j += 256) {
        unsigned w = keysU[j];
        myc += ((w & 0xFFFFu) < T);
        myc += ((w >> 16)     < T);
    }
    scnt[tid] = (unsigned)myc;
    __syncthreads();

    // ---- exclusive scan for deterministic write offsets ----
    unsigned off;
    {
        int w = tid >> 5;
        unsigned v = scnt[tid], inc = v;
        #pragma unroll
        for (int o = 1; o < 32; o <<= 1) {
            unsigned t = __shfl_up_sync(0xFFFFFFFFu, inc, o);
            if (lane >= o) inc += t;
        }
        if (lane == 31) wtot[w] = inc;
        __syncthreads();
        if (tid < 8) {
            unsigned t = wtot[tid], i2 = t;
            #pragma unroll
            for (int o = 1; o < 8; o <<= 1) {
                unsigned x = __shfl_up_sync(0xFFu, i2, o);
                if (tid >= o) i2 += x;
            }
            wtot[tid] = i2 - t;
        }
        __syncthreads();
        off = inc - v + wtot[w];
    }

    // ---- write strictly-smaller indices; collect hi==T tie candidates ----
    for (int j = tid; j < NKV/2; j += 256) {
        unsigned w  = keysU[j];
        unsigned k0 = w & 0xFFFFu, k1 = w >> 16;
        int i0 = 2*j, i1 = 2*j + 1;
        if (k0 < T) { g_topk[base + off] = i0; off++; }
        if (k1 < T) { g_topk[base + off] = i1; off++; }
        bool t0 = (k0 == T), t1 = (k1 == T);
        unsigned m0 = __ballot_sync(0xFFFFFFFFu, t0);
        if (m0) {
            int ld = __ffs(m0) - 1; unsigned b0 = 0;
            if (lane == ld) b0 = atomicAdd(&ctrl[5], (unsigned)__popc(m0));
            b0 = __shfl_sync(0xFFFFFFFFu, b0, ld);
            if (t0) {
                unsigned pos = b0 + __popc(m0 & ((1u << lane) - 1));
                if (pos < TCAP) candI[pos] = (unsigned)i0;
            }
        }
        unsigned m1 = __ballot_sync(0xFFFFFFFFu, t1);
        if (m1) {
            int ld = __ffs(m1) - 1; unsigned b1 = 0;
            if (lane == ld) b1 = atomicAdd(&ctrl[5], (unsigned)__popc(m1));
            b1 = __shfl_sync(0xFFFFFFFFu, b1, ld);
            if (t1) {
                unsigned pos = b1 + __popc(m1 & ((1u << lane) - 1));
                if (pos < TCAP) candI[pos] = (unsigned)i1;
            }
        }
    }
    __syncthreads();

    // ---- full-precision re-rank of the boundary group ----
    int tcount = (int)min(ctrl[5], (unsigned)TCAP);
    for (int t = tid; t < tcount; t += 256) {
        int idx = (int)candI[t];
        candD[t] = d2bits(q0, q1, q2, sq,
                          k_pos[3*idx+0], k_pos[3*idx+1], k_pos[3*idx+2]);
    }
    __syncthreads();
    const int cless = KSEL - kneed;
    for (int t = tid; t < tcount; t += 256) {
        unsigned dt = candD[t], it = candI[t];
        int rank = 0;
        for (int s = 0; s < tcount; s++) {
            unsigned ds = candD[s], is = candI[s];
            rank += (ds < dt) || (ds == dt && is < it);
        }
        if (rank < kneed) g_topk[base + cless + rank] = (int)it;
    }
}

// ---------------------------------------------------------------------------
// Kernel 2: gathered attention + residual(=2x) + LayerNorm. (unchanged)
// ---------------------------------------------------------------------------
__global__ void __launch_bounds__(256)
attend_kernel(const float* __restrict__ q_feat, const float* __restrict__ k_feat,
              const float* __restrict__ v_feat, const float* __restrict__ gamma,
              const float* __restrict__ beta, float* __restrict__ out)
{
    __shared__ float qs[CDIM];
    __shared__ int   ids[KSEL];
    __shared__ float lg[KSEL];
    __shared__ float red[8];

    const int tid  = threadIdx.x;
    const int q    = blockIdx.x;
    const int w    = tid >> 5, lane = tid & 31;

    qs[tid] = q_feat[q*CDIM + tid];
    if (tid < KSEL) ids[tid] = g_topk[q*KSEL + tid];
    __syncthreads();

    for (int n = w; n < KSEL; n += 8) {
        const float* kr = k_feat + (size_t)ids[n] * CDIM;
        float p = 0.f;
        #pragma unroll
        for (int t = 0; t < 8; t++) p = fmaf(qs[lane + 32*t], kr[lane + 32*t], p);
        #pragma unroll
        for (int o = 16; o; o >>= 1) p += __shfl_xor_sync(0xFFFFFFFFu, p, o);
        if (lane == 0) lg[n] = p * 0.0625f;
    }
    __syncthreads();

    if (w == 0) {
        float v0 = lg[lane];
        float v1 = lg[lane + 32];
        float v2 = lg[lane + 64];
        float v3 = (lane < 4) ? lg[lane + 96] : -INFINITY;
        float m = fmaxf(fmaxf(v0, v1), fmaxf(v2, v3));
        #pragma unroll
        for (int o = 16; o; o >>= 1) m = fmaxf(m, __shfl_xor_sync(0xFFFFFFFFu, m, o));
        float e0 = expf(v0 - m), e1 = expf(v1 - m), e2 = expf(v2 - m);
        float e3 = (lane < 4) ? expf(v3 - m) : 0.f;
        float s = e0 + e1 + e2 + e3;
        #pragma unroll
        for (int o = 16; o; o >>= 1) s += __shfl_xor_sync(0xFFFFFFFFu, s, o);
        float inv = 1.0f / s;
        lg[lane]       = e0 * inv;
        lg[lane + 32]  = e1 * inv;
        lg[lane + 64]  = e2 * inv;
        if (lane < 4) lg[lane + 96] = e3 * inv;
    }
    __syncthreads();

    float a0 = 0.f, a1 = 0.f, a2 = 0.f, a3 = 0.f;
    for (int n = 0; n < KSEL; n += 4) {
        a0 = fmaf(lg[n+0], v_feat[(size_t)ids[n+0]*CDIM + tid], a0);
        a1 = fmaf(lg[n+1], v_feat[(size_t)ids[n+1]*CDIM + tid], a1);
        a2 = fmaf(lg[n+2], v_feat[(size_t)ids[n+2]*CDIM + tid], a2);
        a3 = fmaf(lg[n+3], v_feat[(size_t)ids[n+3]*CDIM + tid], a3);
    }
    float y = 2.0f * ((a0 + a1) + (a2 + a3));

    float s = y;
    #pragma unroll
    for (int o = 16; o; o >>= 1) s += __shfl_xor_sync(0xFFFFFFFFu, s, o);
    if (lane == 0) red[w] = s;
    __syncthreads();
    float tot = 0.f;
    #pragma unroll
    for (int i = 0; i < 8; i++) tot += red[i];
    float mean = tot * (1.0f / CDIM);
    float d = y - mean;
    float s2 = d * d;
    __syncthreads();
    #pragma unroll
    for (int o = 16; o; o >>= 1) s2 += __shfl_xor_sync(0xFFFFFFFFu, s2, o);
    if (lane == 0) red[w] = s2;
    __syncthreads();
    float tot2 = 0.f;
    #pragma unroll
    for (int i = 0; i < 8; i++) tot2 += red[i];
    float var = tot2 * (1.0f / CDIM);

    out[q*CDIM + tid] = d * rsqrtf(var + 1e-5f) * gamma[tid] + beta[tid];
}

// ---------------------------------------------------------------------------
extern "C" void kernel_launch(void* const* d_in, const int* in_sizes, int n_in,
                              void* d_out, int out_size)
{
    const float* q_feat = (const float*)d_in[1];
    const float* k_feat = (const float*)d_in[2];
    const float* v_feat = (const float*)d_in[3];
    const float* q_pos  = (const float*)d_in[4];
    const float* k_pos  = (const float*)d_in[5];
    const float* gamma  = (const float*)d_in[6];
    const float* beta   = (const float*)d_in[7];
    float* out = (float*)d_out;

    size_t smem = (size_t)(NKV/2 + 16*256 + 16 + 8 + CCAP + TCAP + TCAP + 256 + 8)
                  * sizeof(unsigned);
    cudaFuncSetAttribute(select_kernel,
                         cudaFuncAttributeMaxDynamicSharedMemorySize, (int)smem);

    select_kernel<<<NQ, 256, smem>>>(q_pos, k_pos);
    attend_kernel<<<NQ, 256>>>(q_feat, k_feat, v_feat, gamma, beta, out);
}

// round 13
// speedup vs baseline: 2.4850x; 1.3623x over previous
#include <cuda_runtime.h>
#include <math.h>

#define NQ   4096
#define NKV  32768
#define CDIM 256
#define KSEL 100
#define CCAP 4096
#define TCAP 512

__device__ int g_topk[NQ * KSEL];

// Identical arithmetic in the distance pass and the tie-recompute path.
__device__ __forceinline__ unsigned d2bits(float q0, float q1, float q2, float sq,
                                           float kx, float ky, float kz)
{
    float dot = kx*q0 + ky*q1 + kz*q2;
    float sk  = kx*kx + ky*ky + kz*kz;
    float d2  = sq + sk - 2.0f*dot;      // same expansion as reference
    return __float_as_uint(fmaxf(d2, 0.0f));
}

// Exclusive scan of v over 256 threads. Contains 2 barriers; call uniformly.
__device__ __forceinline__ unsigned block_exscan(unsigned v, unsigned* wtot,
                                                 int tid, int lane)
{
    unsigned inc = v;
    #pragma unroll
    for (int o = 1; o < 32; o <<= 1) {
        unsigned t = __shfl_up_sync(0xFFFFFFFFu, inc, o);
        if (lane >= o) inc += t;
    }
    const int w = tid >> 5;
    if (lane == 31) wtot[w] = inc;
    __syncthreads();
    unsigned woff = 0;
    #pragma unroll
    for (int i = 0; i < 8; i++) woff += (i < w) ? wtot[i] : 0u;
    __syncthreads();                      // allow wtot reuse by later calls
    return woff + inc - v;
}

// ---------------------------------------------------------------------------
// Kernel 1: exact top-100 NN per query. 16-bit-key radix select in smem.
//  pass0 (bits 15:12) fused into the distance pass (totals only — per-thread
//    strict-less counts are recomputed in the pass-1 scan so that ALL offset
//    math uses the same thread->element (pair) mapping as the write loop)
//  pass1 (bits 11:8) count scan; then ONE compact scan that
//    - writes all strictly-smaller (by 8-bit prefix) indices straight to
//      g_topk at deterministic scan offsets (no atomics)
//    - compacts the equal-prefix group as (key<<16|idx) pairs
//  passes 2,3 + finale run on the compact array only (~1K elements).
//  Boundary (key==T) re-ranked at full fp32 precision (+idx) -> exact set.
// ---------------------------------------------------------------------------
__global__ void __launch_bounds__(256, 2)
select_kernel(const float* __restrict__ q_pos, const float* __restrict__ k_pos)
{
    extern __shared__ unsigned smem_u[];
    unsigned* keysU    = smem_u;              // NKV/2 packed ushort keys
    unsigned* hist     = keysU + NKV/2;       // 16*256 per-thread rows
    unsigned* binTotal = hist + 16*256;       // 16
    unsigned* ctrl     = binTotal + 16;       // 8
    unsigned* cbits    = ctrl + 8;            // CCAP (key<<16|idx)
    unsigned* candI    = cbits + CCAP;        // TCAP tie indices
    unsigned* candD    = candI + TCAP;        // TCAP tie d2 bits
    unsigned* wtot     = candD + TCAP;        // 8 scan scratch

    const int tid  = threadIdx.x;
    const int lane = tid & 31;
    const int q    = blockIdx.x;
    const int base = q * KSEL;

    const float q0 = q_pos[3*q+0], q1 = q_pos[3*q+1], q2 = q_pos[3*q+2];
    const float sq = q0*q0 + q1*q1 + q2*q2;

    #pragma unroll
    for (int b = 0; b < 16; b++) hist[b*256 + tid] = 0;

    // ---- distance pass (fused pass-0 histogram on bits 15:12) ----
    // NOTE: this histogram is used ONLY for bin TOTALS (mapping-independent).
    const float4* kp4 = (const float4*)k_pos;
    for (int g = tid; g < NKV/4; g += 256) {
        float4 A = kp4[3*g+0];
        float4 B = kp4[3*g+1];
        float4 C = kp4[3*g+2];
        float kx[4] = {A.x, A.w, B.z, C.y};
        float ky[4] = {A.y, B.x, B.w, C.z};
        float kz[4] = {A.z, B.y, C.x, C.w};
        unsigned k16[4];
        #pragma unroll
        for (int m = 0; m < 4; m++) {
            unsigned key = d2bits(q0, q1, q2, sq, kx[m], ky[m], kz[m]) >> 16;
            hist[(key >> 12)*256 + tid]++;
            k16[m] = key;
        }
        ((uint2*)keysU)[g] = make_uint2(k16[0] | (k16[1] << 16),
                                        k16[2] | (k16[3] << 16));
    }
    __syncthreads();

    // ---- pass 0: reduce + select ----
    {
        int w = tid >> 5, bin = 2*w + (lane >> 4), l16 = lane & 15;
        unsigned s = 0;
        #pragma unroll
        for (int i = 0; i < 16; i++) s += hist[bin*256 + l16 + 16*i];
        s += __shfl_xor_sync(0xFFFFFFFFu, s, 8);
        s += __shfl_xor_sync(0xFFFFFFFFu, s, 4);
        s += __shfl_xor_sync(0xFFFFFFFFu, s, 2);
        s += __shfl_xor_sync(0xFFFFFFFFu, s, 1);
        if (l16 == 0) binTotal[bin] = s;
    }
    __syncthreads();
    if (tid == 0) {
        unsigned cum = 0, cnt = 0; int b = 0;
        for (b = 0; b < 16; b++) {
            cnt = binTotal[b];
            if (cum + cnt >= (unsigned)KSEL) break;
            cum += cnt;
        }
        ctrl[0] = (unsigned)b;
        ctrl[1] = (unsigned)KSEL - cum;
    }
    __syncthreads();
    const unsigned b0 = ctrl[0];
    int kneed = (int)ctrl[1];

    #pragma unroll
    for (int b = 0; b < 16; b++) hist[b*256 + tid] = 0;   // own column only

    // ---- pass 1: count scan over full array (PAIR mapping: j -> {2j,2j+1})
    //      also recompute per-thread strict-less-top4 count in THIS mapping.
    unsigned S0j = 0;
    for (int j = tid; j < NKV/2; j += 256) {
        unsigned w  = keysU[j];
        unsigned k0 = w & 0xFFFFu, k1 = w >> 16;
        unsigned t0 = k0 >> 12,    t1 = k1 >> 12;
        S0j += (t0 < b0) + (t1 < b0);
        if (t0 == b0) hist[((k0 >> 8) & 15u)*256 + tid]++;
        if (t1 == b0) hist[((k1 >> 8) & 15u)*256 + tid]++;
    }
    __syncthreads();
    {
        int w = tid >> 5, bin = 2*w + (lane >> 4), l16 = lane & 15;
        unsigned s = 0;
        #pragma unroll
        for (int i = 0; i < 16; i++) s += hist[bin*256 + l16 + 16*i];
        s += __shfl_xor_sync(0xFFFFFFFFu, s, 8);
        s += __shfl_xor_sync(0xFFFFFFFFu, s, 4);
        s += __shfl_xor_sync(0xFFFFFFFFu, s, 2);
        s += __shfl_xor_sync(0xFFFFFFFFu, s, 1);
        if (l16 == 0) binTotal[bin] = s;
    }
    __syncthreads();
    if (tid == 0) {
        unsigned cum = 0, cnt = 0; int b = 0;
        for (b = 0; b < 16; b++) {
            cnt = binTotal[b];
            if (cum + cnt >= (unsigned)kneed) break;
            cum += cnt;
        }
        ctrl[0] = (unsigned)b;
        ctrl[1] = (unsigned)kneed - cum;
        ctrl[3] = cnt;
    }
    __syncthreads();
    const unsigned b1   = ctrl[0];
    kneed                = (int)ctrl[1];
    const unsigned cnt1 = ctrl[3];
    unsigned prefix = (b0 << 4) | b1;          // 8-bit prefix of the 100th key
    const int cum1  = KSEL - kneed;            // strict-less (8-bit prefix) count
    const bool compacted = (cnt1 <= CCAP);

    unsigned S1 = 0;                           // pair-mapping per-thread counts
    for (unsigned b = 0; b < b1; b++) S1 += hist[b*256 + tid];
    const unsigned E1 = hist[b1*256 + tid];

    int curN = -1;
    if (compacted) {
        // one packed exclusive scan gives both offset streams, SAME j mapping
        unsigned ps   = block_exscan(((S0j + S1) << 16) | E1, wtot, tid, lane);
        unsigned sOff = ps >> 16;
        unsigned eOff = ps & 0xFFFFu;
        for (int j = tid; j < NKV/2; j += 256) {
            unsigned w  = keysU[j];
            unsigned k0 = w & 0xFFFFu, k1 = w >> 16;
            unsigned h0 = k0 >> 8,     h1 = k1 >> 8;
            int i0 = 2*j, i1 = 2*j + 1;
            if (h0 < prefix)       { g_topk[base + sOff] = i0; sOff++; }
            else if (h0 == prefix) { cbits[eOff] = (k0 << 16) | (unsigned)i0; eOff++; }
            if (h1 < prefix)       { g_topk[base + sOff] = i1; sOff++; }
            else if (h1 == prefix) { cbits[eOff] = (k1 << 16) | (unsigned)i1; eOff++; }
        }
        __syncthreads();
        curN = (int)cnt1;
    }

    // ---- passes 2,3 ----
    #pragma unroll
    for (int p = 2; p < 4; p++) {
        const int shift = 12 - 4*p;            // 4, then 0
        #pragma unroll
        for (int b = 0; b < 16; b++) hist[b*256 + tid] = 0;
        if (curN >= 0) {
            for (int j = tid; j < curN; j += 256) {
                unsigned k = cbits[j] >> 16;
                if ((k >> (shift+4)) == prefix) hist[((k >> shift) & 15u)*256 + tid]++;
            }
        } else {
            for (int j = tid; j < NKV/2; j += 256) {
                unsigned w  = keysU[j];
                unsigned k0 = w & 0xFFFFu, k1 = w >> 16;
                if ((k0 >> (shift+4)) == prefix) hist[((k0 >> shift) & 15u)*256 + tid]++;
                if ((k1 >> (shift+4)) == prefix) hist[((k1 >> shift) & 15u)*256 + tid]++;
            }
        }
        __syncthreads();
        {
            int w = tid >> 5, bin = 2*w + (lane >> 4), l16 = lane & 15;
            unsigned s = 0;
            #pragma unroll
            for (int i = 0; i < 16; i++) s += hist[bin*256 + l16 + 16*i];
            s += __shfl_xor_sync(0xFFFFFFFFu, s, 8);
            s += __shfl_xor_sync(0xFFFFFFFFu, s, 4);
            s += __shfl_xor_sync(0xFFFFFFFFu, s, 2);
            s += __shfl_xor_sync(0xFFFFFFFFu, s, 1);
            if (l16 == 0) binTotal[bin] = s;
        }
        __syncthreads();
        if (tid == 0) {
            unsigned cum = 0, cnt = 0; int b = 0;
            for (b = 0; b < 16; b++) {
                cnt = binTotal[b];
                if (cum + cnt >= (unsigned)kneed) break;
                cum += cnt;
            }
            ctrl[0] = (unsigned)b;
            ctrl[1] = (unsigned)kneed - cum;
            ctrl[5] = 0;                       // tie counter for finale
        }
        __syncthreads();
        prefix = (prefix << 4) | ctrl[0];
        kneed  = (int)ctrl[1];
        __syncthreads();
    }

    const unsigned T = prefix;                 // full 16-bit key of the 100th
    const int kneedF = kneed;
    const int cless  = KSEL - kneedF;

    // ---- finale ----
    if (compacted) {
        unsigned c = 0;
        for (int j = tid; j < curN; j += 256) c += ((cbits[j] >> 16) < T);
        unsigned off = block_exscan(c, wtot, tid, lane) + (unsigned)cum1;
        for (int j = tid; j < curN; j += 256) {
            unsigned cw  = cbits[j];
            unsigned key = cw >> 16, idx = cw & 0xFFFFu;
            if (key < T)       { g_topk[base + off] = (int)idx; off++; }
            else if (key == T) {
                unsigned p = atomicAdd(&ctrl[5], 1u);
                if (p < TCAP) candI[p] = idx;
            }
        }
    } else {
        unsigned c = 0;
        for (int j = tid; j < NKV/2; j += 256) {
            unsigned w = keysU[j];
            c += ((w & 0xFFFFu) < T) + ((w >> 16) < T);
        }
        unsigned off = block_exscan(c, wtot, tid, lane);
        for (int j = tid; j < NKV/2; j += 256) {
            unsigned w  = keysU[j];
            unsigned k0 = w & 0xFFFFu, k1 = w >> 16;
            int i0 = 2*j, i1 = 2*j + 1;
            if (k0 < T)       { g_topk[base + off] = i0; off++; }
            else if (k0 == T) {
                unsigned p = atomicAdd(&ctrl[5], 1u);
                if (p < TCAP) candI[p] = (unsigned)i0;
            }
            if (k1 < T)       { g_topk[base + off] = i1; off++; }
            else if (k1 == T) {
                unsigned p = atomicAdd(&ctrl[5], 1u);
                if (p < TCAP) candI[p] = (unsigned)i1;
            }
        }
    }
    __syncthreads();

    // full-precision re-rank of the boundary group (order-independent -> deterministic)
    int tcount = (int)min(ctrl[5], (unsigned)TCAP);
    for (int t = tid; t < tcount; t += 256) {
        int idx = (int)candI[t];
        candD[t] = d2bits(q0, q1, q2, sq,
                          k_pos[3*idx+0], k_pos[3*idx+1], k_pos[3*idx+2]);
    }
    __syncthreads();
    for (int t = tid; t < tcount; t += 256) {
        unsigned dt = candD[t], it = candI[t];
        int rank = 0;
        for (int s = 0; s < tcount; s++) {
            unsigned ds = candD[s], is = candI[s];
            rank += (ds < dt) || (ds == dt && is < it);
        }
        if (rank < kneedF) g_topk[base + cless + rank] = (int)it;
    }
}

// ---------------------------------------------------------------------------
// Kernel 2: gathered attention + residual(=2x) + LayerNorm. (unchanged — at
// its L2 gather roof: 67us measured vs ~75us model)
// ---------------------------------------------------------------------------
__global__ void __launch_bounds__(256)
attend_kernel(const float* __restrict__ q_feat, const float* __restrict__ k_feat,
              const float* __restrict__ v_feat, const float* __restrict__ gamma,
              const float* __restrict__ beta, float* __restrict__ out)
{
    __shared__ float qs[CDIM];
    __shared__ int   ids[KSEL];
    __shared__ float lg[KSEL];
    __shared__ float red[8];

    const int tid  = threadIdx.x;
    const int q    = blockIdx.x;
    const int w    = tid >> 5, lane = tid & 31;

    qs[tid] = q_feat[q*CDIM + tid];
    if (tid < KSEL) ids[tid] = g_topk[q*KSEL + tid];
    __syncthreads();

    for (int n = w; n < KSEL; n += 8) {
        const float* kr = k_feat + (size_t)ids[n] * CDIM;
        float p = 0.f;
        #pragma unroll
        for (int t = 0; t < 8; t++) p = fmaf(qs[lane + 32*t], kr[lane + 32*t], p);
        #pragma unroll
        for (int o = 16; o; o >>= 1) p += __shfl_xor_sync(0xFFFFFFFFu, p, o);
        if (lane == 0) lg[n] = p * 0.0625f;
    }
    __syncthreads();

    if (w == 0) {
        float v0 = lg[lane];
        float v1 = lg[lane + 32];
        float v2 = lg[lane + 64];
        float v3 = (lane < 4) ? lg[lane + 96] : -INFINITY;
        float m = fmaxf(fmaxf(v0, v1), fmaxf(v2, v3));
        #pragma unroll
        for (int o = 16; o; o >>= 1) m = fmaxf(m, __shfl_xor_sync(0xFFFFFFFFu, m, o));
        float e0 = expf(v0 - m), e1 = expf(v1 - m), e2 = expf(v2 - m);
        float e3 = (lane < 4) ? expf(v3 - m) : 0.f;
        float s = e0 + e1 + e2 + e3;
        #pragma unroll
        for (int o = 16; o; o >>= 1) s += __shfl_xor_sync(0xFFFFFFFFu, s, o);
        float inv = 1.0f / s;
        lg[lane]       = e0 * inv;
        lg[lane + 32]  = e1 * inv;
        lg[lane + 64]  = e2 * inv;
        if (lane < 4) lg[lane + 96] = e3 * inv;
    }
    __syncthreads();

    float a0 = 0.f, a1 = 0.f, a2 = 0.f, a3 = 0.f;
    for (int n = 0; n < KSEL; n += 4) {
        a0 = fmaf(lg[n+0], v_feat[(size_t)ids[n+0]*CDIM + tid], a0);
        a1 = fmaf(lg[n+1], v_feat[(size_t)ids[n+1]*CDIM + tid], a1);
        a2 = fmaf(lg[n+2], v_feat[(size_t)ids[n+2]*CDIM + tid], a2);
        a3 = fmaf(lg[n+3], v_feat[(size_t)ids[n+3]*CDIM + tid], a3);
    }
    float y = 2.0f * ((a0 + a1) + (a2 + a3));

    float s = y;
    #pragma unroll
    for (int o = 16; o; o >>= 1) s += __shfl_xor_sync(0xFFFFFFFFu, s, o);
    if (lane == 0) red[w] = s;
    __syncthreads();
    float tot = 0.f;
    #pragma unroll
    for (int i = 0; i < 8; i++) tot += red[i];
    float mean = tot * (1.0f / CDIM);
    float d = y - mean;
    float s2 = d * d;
    __syncthreads();
    #pragma unroll
    for (int o = 16; o; o >>= 1) s2 += __shfl_xor_sync(0xFFFFFFFFu, s2, o);
    if (lane == 0) red[w] = s2;
    __syncthreads();
    float tot2 = 0.f;
    #pragma unroll
    for (int i = 0; i < 8; i++) tot2 += red[i];
    float var = tot2 * (1.0f / CDIM);

    out[q*CDIM + tid] = d * rsqrtf(var + 1e-5f) * gamma[tid] + beta[tid];
}

// ---------------------------------------------------------------------------
extern "C" void kernel_launch(void* const* d_in, const int* in_sizes, int n_in,
                              void* d_out, int out_size)
{
    const float* q_feat = (const float*)d_in[1];
    const float* k_feat = (const float*)d_in[2];
    const float* v_feat = (const float*)d_in[3];
    const float* q_pos  = (const float*)d_in[4];
    const float* k_pos  = (const float*)d_in[5];
    const float* gamma  = (const float*)d_in[6];
    const float* beta   = (const float*)d_in[7];
    float* out = (float*)d_out;

    size_t smem = (size_t)(NKV/2 + 16*256 + 16 + 8 + CCAP + TCAP + TCAP + 8)
                  * sizeof(unsigned);
    cudaFuncSetAttribute(select_kernel,
                         cudaFuncAttributeMaxDynamicSharedMemorySize, (int)smem);

    select_kernel<<<NQ, 256, smem>>>(q_pos, k_pos);
    attend_kernel<<<NQ, 256>>>(q_feat, k_feat, v_feat, gamma, beta, out);
}

// round 16
// speedup vs baseline: 2.4977x; 1.0051x over previous
#include <cuda_runtime.h>
#include <math.h>

#define NQ   4096
#define NKV  32768
#define CDIM 256
#define KSEL 100
#define CCAP 4096
#define TCAP 512
#define NBIN 17            // 16 real bins + 1 trash bin (unconditional updates)

// Identical arithmetic in the distance pass and the tie-recompute path.
__device__ __forceinline__ unsigned d2bits(float q0, float q1, float q2, float sq,
                                           float kx, float ky, float kz)
{
    float dot = kx*q0 + ky*q1 + kz*q2;
    float sk  = kx*kx + ky*ky + kz*kz;
    float d2  = sq + sk - 2.0f*dot;      // same expansion as reference
    return __float_as_uint(fmaxf(d2, 0.0f));
}

// Exclusive scan of v over 256 threads. Contains 2 barriers; call uniformly.
__device__ __forceinline__ unsigned block_exscan(unsigned v, unsigned* wtot,
                                                 int tid, int lane)
{
    unsigned inc = v;
    #pragma unroll
    for (int o = 1; o < 32; o <<= 1) {
        unsigned t = __shfl_up_sync(0xFFFFFFFFu, inc, o);
        if (lane >= o) inc += t;
    }
    const int w = tid >> 5;
    if (lane == 31) wtot[w] = inc;
    __syncthreads();
    unsigned woff = 0;
    #pragma unroll
    for (int i = 0; i < 8; i++) woff += (i < w) ? wtot[i] : 0u;
    __syncthreads();
    return woff + inc - v;
}

// ---------------------------------------------------------------------------
// Fused kernel: exact top-100 NN select (16-bit radix, smem) + attention + LN.
// One CTA (256 thr) per query, 2 CTAs/SM.
// Histograms: byte counters, 4 slots per (bin,thread) so a 4-key batch updates
// provably-distinct addresses (loads batch before stores -> no RMW chains).
// Trash bin 16 makes out-of-scope updates unconditional.
// ---------------------------------------------------------------------------
__global__ void __launch_bounds__(256, 2)
fused_kernel(const float* __restrict__ q_pos,  const float* __restrict__ k_pos,
             const float* __restrict__ q_feat, const float* __restrict__ k_feat,
             const float* __restrict__ v_feat, const float* __restrict__ gamma,
             const float* __restrict__ beta,   float* __restrict__ out)
{
    extern __shared__ unsigned smem_u[];
    unsigned* keysU    = smem_u;                    // NKV/2 packed ushort keys
    unsigned* histW    = keysU + NKV/2;             // NBIN*256 words (byte hist)
    unsigned char* histB = (unsigned char*)histW;   // idx = (bin<<10)|(tid<<2)|slot
    unsigned* binTotal = histW + NBIN*256;          // 16
    unsigned* ctrl     = binTotal + 16;             // 8
    unsigned* cbits    = ctrl + 8;                  // CCAP (key<<16|idx)
    unsigned* candI    = cbits + CCAP;              // TCAP tie indices
    unsigned* candD    = candI + TCAP;              // TCAP tie d2 bits
    unsigned* wtot     = candD + TCAP;              // 8 scan scratch
    int*      ids_s    = (int*)(wtot + 8);          // 128 selected indices
    float*    qs       = (float*)(ids_s + 128);     // 256 query features
    float*    lg       = (float*)(qs + CDIM);       // 128 logits/probs
    float*    red      = (float*)(lg + 128);        // 8 LN reduce

    const int tid  = threadIdx.x;
    const int lane = tid & 31;
    const int q    = blockIdx.x;

    const float q0 = q_pos[3*q+0], q1 = q_pos[3*q+1], q2 = q_pos[3*q+2];
    const float sq = q0*q0 + q1*q1 + q2*q2;

    // zero byte-hist (own data only; per-thread rows are private)
    for (int i = tid; i < NBIN*256; i += 256) histW[i] = 0;

    // ================= distance pass (fused pass-0 hist, bits 15:12) ========
    // 2 groups of 4 keys per iteration: 6 LDG.128 up front for MLP.
    const float4* kp4 = (const float4*)k_pos;
    for (int t = 0; t < 16; t++) {
        const int g1 = tid + 512*t, g2 = g1 + 256;
        float4 A1 = kp4[3*g1+0], B1 = kp4[3*g1+1], C1 = kp4[3*g1+2];
        float4 A2 = kp4[3*g2+0], B2 = kp4[3*g2+1], C2 = kp4[3*g2+2];
        unsigned ka[4], kb[4];
        {
            float kx[4] = {A1.x, A1.w, B1.z, C1.y};
            float ky[4] = {A1.y, B1.x, B1.w, C1.z};
            float kz[4] = {A1.z, B1.y, C1.x, C1.w};
            #pragma unroll
            for (int m = 0; m < 4; m++)
                ka[m] = d2bits(q0, q1, q2, sq, kx[m], ky[m], kz[m]) >> 16;
        }
        {
            float kx[4] = {A2.x, A2.w, B2.z, C2.y};
            float ky[4] = {A2.y, B2.x, B2.w, C2.z};
            float kz[4] = {A2.z, B2.y, C2.x, C2.w};
            #pragma unroll
            for (int m = 0; m < 4; m++)
                kb[m] = d2bits(q0, q1, q2, sq, kx[m], ky[m], kz[m]) >> 16;
        }
        // batch A: 4 distinct slot addresses -> 4 LDS then 4 STS
        {
            unsigned i0 = ((ka[0] >> 12) << 10) | (tid << 2) | 0u;
            unsigned i1 = ((ka[1] >> 12) << 10) | (tid << 2) | 1u;
            unsigned i2 = ((ka[2] >> 12) << 10) | (tid << 2) | 2u;
            unsigned i3 = ((ka[3] >> 12) << 10) | (tid << 2) | 3u;
            unsigned char c0 = histB[i0], c1 = histB[i1], c2 = histB[i2], c3 = histB[i3];
            histB[i0] = c0+1; histB[i1] = c1+1; histB[i2] = c2+1; histB[i3] = c3+1;
        }
        // batch B
        {
            unsigned i0 = ((kb[0] >> 12) << 10) | (tid << 2) | 0u;
            unsigned i1 = ((kb[1] >> 12) << 10) | (tid << 2) | 1u;
            unsigned i2 = ((kb[2] >> 12) << 10) | (tid << 2) | 2u;
            unsigned i3 = ((kb[3] >> 12) << 10) | (tid << 2) | 3u;
            unsigned char c0 = histB[i0], c1 = histB[i1], c2 = histB[i2], c3 = histB[i3];
            histB[i0] = c0+1; histB[i1] = c1+1; histB[i2] = c2+1; histB[i3] = c3+1;
        }
        ((uint2*)keysU)[g1] = make_uint2(ka[0] | (ka[1] << 16), ka[2] | (ka[3] << 16));
        ((uint2*)keysU)[g2] = make_uint2(kb[0] | (kb[1] << 16), kb[2] | (kb[3] << 16));
    }
    __syncthreads();

    // ---- pass 0: dp4a reduce (sums 4 slots per LDS.32) + pivot ----
    {
        int w = tid >> 5, bin = 2*w + (lane >> 4), l16 = lane & 15;
        int s = 0;
        #pragma unroll
        for (int i = 0; i < 16; i++)
            s = __dp4a((int)histW[(bin << 8) + l16 + 16*i], 0x01010101, s);
        s += __shfl_xor_sync(0xFFFFFFFFu, s, 8);
        s += __shfl_xor_sync(0xFFFFFFFFu, s, 4);
        s += __shfl_xor_sync(0xFFFFFFFFu, s, 2);
        s += __shfl_xor_sync(0xFFFFFFFFu, s, 1);
        if (l16 == 0) binTotal[bin] = (unsigned)s;
    }
    __syncthreads();
    if (tid == 0) {
        unsigned cum = 0, cnt = 0; int b = 0;
        for (b = 0; b < 16; b++) {
            cnt = binTotal[b];
            if (cum + cnt >= (unsigned)KSEL) break;
            cum += cnt;
        }
        ctrl[0] = (unsigned)b;
        ctrl[1] = (unsigned)KSEL - cum;
    }
    __syncthreads();
    const unsigned b0 = ctrl[0];
    int kneed = (int)ctrl[1];

    for (int i = tid; i < NBIN*256; i += 256) histW[i] = 0;   // own rows only
    __syncthreads();   // previous dp4a reads other columns; order zero after them

    // ================= pass 1 (bits 11:8) — PAIR mapping j -> {2j,2j+1} ======
    unsigned S0j = 0;
    for (int t = 0; t < 32; t++) {
        const int j1 = tid + 512*t, j2 = j1 + 256;
        unsigned w1 = keysU[j1], w2 = keysU[j2];       // 2 LDS up front
        unsigned k0 = w1 & 0xFFFFu, k1 = w1 >> 16;
        unsigned k2 = w2 & 0xFFFFu, k3 = w2 >> 16;
        unsigned t0 = k0 >> 12, t1 = k1 >> 12, t2 = k2 >> 12, t3 = k3 >> 12;
        S0j += (t0 < b0) + (t1 < b0) + (t2 < b0) + (t3 < b0);
        unsigned bn0 = (t0 == b0) ? ((k0 >> 8) & 15u) : 16u;
        unsigned bn1 = (t1 == b0) ? ((k1 >> 8) & 15u) : 16u;
        unsigned bn2 = (t2 == b0) ? ((k2 >> 8) & 15u) : 16u;
        unsigned bn3 = (t3 == b0) ? ((k3 >> 8) & 15u) : 16u;
        unsigned i0 = (bn0 << 10) | (tid << 2) | 0u;
        unsigned i1 = (bn1 << 10) | (tid << 2) | 1u;
        unsigned i2 = (bn2 << 10) | (tid << 2) | 2u;
        unsigned i3 = (bn3 << 10) | (tid << 2) | 3u;
        unsigned char c0 = histB[i0], c1 = histB[i1], c2 = histB[i2], c3 = histB[i3];
        histB[i0] = c0+1; histB[i1] = c1+1; histB[i2] = c2+1; histB[i3] = c3+1;
    }
    __syncthreads();
    {
        int w = tid >> 5, bin = 2*w + (lane >> 4), l16 = lane & 15;
        int s = 0;
        #pragma unroll
        for (int i = 0; i < 16; i++)
            s = __dp4a((int)histW[(bin << 8) + l16 + 16*i], 0x01010101, s);
        s += __shfl_xor_sync(0xFFFFFFFFu, s, 8);
        s += __shfl_xor_sync(0xFFFFFFFFu, s, 4);
        s += __shfl_xor_sync(0xFFFFFFFFu, s, 2);
        s += __shfl_xor_sync(0xFFFFFFFFu, s, 1);
        if (l16 == 0) binTotal[bin] = (unsigned)s;
    }
    __syncthreads();
    if (tid == 0) {
        unsigned cum = 0, cnt = 0; int b = 0;
        for (b = 0; b < 16; b++) {
            cnt = binTotal[b];
            if (cum + cnt >= (unsigned)kneed) break;
            cum += cnt;
        }
        ctrl[0] = (unsigned)b;
        ctrl[1] = (unsigned)kneed - cum;
        ctrl[3] = cnt;
    }
    __syncthreads();
    const unsigned b1   = ctrl[0];
    kneed                = (int)ctrl[1];
    const unsigned cnt1 = ctrl[3];
    unsigned prefix = (b0 << 4) | b1;          // 8-bit prefix of the 100th key
    const int cum1  = KSEL - kneed;            // strict-less (8-bit prefix) count
    const bool compacted = (cnt1 <= CCAP);

    // per-thread S1/E1 from own hist column (same pair mapping as pass 1)
    unsigned S1 = 0;
    for (unsigned b = 0; b < b1; b++)
        S1 = (unsigned)__dp4a((int)histW[(b << 8) + tid], 0x01010101, (int)S1);
    const unsigned E1 =
        (unsigned)__dp4a((int)histW[(b1 << 8) + tid], 0x01010101, 0);

    int curN = -1;
    if (compacted) {
        // one packed exclusive scan -> both offset streams, SAME j mapping
        unsigned ps   = block_exscan(((S0j + S1) << 16) | E1, wtot, tid, lane);
        unsigned sOff = ps >> 16;
        unsigned eOff = ps & 0xFFFFu;
        for (int t = 0; t < 32; t++) {
            const int j1 = tid + 512*t, j2 = j1 + 256;
            unsigned w1 = keysU[j1], w2 = keysU[j2];
            unsigned k0 = w1 & 0xFFFFu, k1 = w1 >> 16;
            unsigned k2 = w2 & 0xFFFFu, k3 = w2 >> 16;
            unsigned h0 = k0 >> 8, h1 = k1 >> 8, h2 = k2 >> 8, h3 = k3 >> 8;
            if (h0 < prefix)       { ids_s[sOff] = 2*j1;   sOff++; }
            else if (h0 == prefix) { cbits[eOff] = (k0 << 16) | (unsigned)(2*j1);   eOff++; }
            if (h1 < prefix)       { ids_s[sOff] = 2*j1+1; sOff++; }
            else if (h1 == prefix) { cbits[eOff] = (k1 << 16) | (unsigned)(2*j1+1); eOff++; }
            if (h2 < prefix)       { ids_s[sOff] = 2*j2;   sOff++; }
            else if (h2 == prefix) { cbits[eOff] = (k2 << 16) | (unsigned)(2*j2);   eOff++; }
            if (h3 < prefix)       { ids_s[sOff] = 2*j2+1; sOff++; }
            else if (h3 == prefix) { cbits[eOff] = (k3 << 16) | (unsigned)(2*j2+1); eOff++; }
        }
        __syncthreads();
        curN = (int)cnt1;
    }

    // ================= passes 2,3 ==========================================
    #pragma unroll
    for (int p = 2; p < 4; p++) {
        const int shift = 12 - 4*p;            // 4, then 0
        #pragma unroll
        for (int b = 0; b < NBIN; b++) histW[(b << 8) + tid] = 0;  // own column
        if (curN >= 0) {
            for (int j = tid; j < curN; j += 256) {
                unsigned k = cbits[j] >> 16;
                unsigned bn = ((k >> (shift+4)) == prefix) ? ((k >> shift) & 15u) : 16u;
                histB[(bn << 10) | (tid << 2)]++;          // slot 0, <=16/thread
            }
        } else {
            for (int j = tid; j < NKV/2; j += 256) {
                unsigned w  = keysU[j];
                unsigned k0 = w & 0xFFFFu, k1 = w >> 16;
                unsigned bn0 = ((k0 >> (shift+4)) == prefix) ? ((k0 >> shift) & 15u) : 16u;
                unsigned bn1 = ((k1 >> (shift+4)) == prefix) ? ((k1 >> shift) & 15u) : 16u;
                unsigned i0 = (bn0 << 10) | (tid << 2) | 0u;
                unsigned i1 = (bn1 << 10) | (tid << 2) | 1u;
                unsigned char c0 = histB[i0], c1 = histB[i1];
                histB[i0] = c0+1; histB[i1] = c1+1;
            }
        }
        __syncthreads();
        {
            int w = tid >> 5, bin = 2*w + (lane >> 4), l16 = lane & 15;
            int s = 0;
            #pragma unroll
            for (int i = 0; i < 16; i++)
                s = __dp4a((int)histW[(bin << 8) + l16 + 16*i], 0x01010101, s);
            s += __shfl_xor_sync(0xFFFFFFFFu, s, 8);
            s += __shfl_xor_sync(0xFFFFFFFFu, s, 4);
            s += __shfl_xor_sync(0xFFFFFFFFu, s, 2);
            s += __shfl_xor_sync(0xFFFFFFFFu, s, 1);
            if (l16 == 0) binTotal[bin] = (unsigned)s;
        }
        __syncthreads();
        if (tid == 0) {
            unsigned cum = 0, cnt = 0; int b = 0;
            for (b = 0; b < 16; b++) {
                cnt = binTotal[b];
                if (cum + cnt >= (unsigned)kneed) break;
                cum += cnt;
            }
            ctrl[0] = (unsigned)b;
            ctrl[1] = (unsigned)kneed - cum;
            ctrl[5] = 0;                       // tie counter for finale
        }
        __syncthreads();
        prefix = (prefix << 4) | ctrl[0];
        kneed  = (int)ctrl[1];
        __syncthreads();
    }

    const unsigned T = prefix;                 // full 16-bit key of the 100th
    const int kneedF = kneed;
    const int cless  = KSEL - kneedF;

    // ================= finale ==============================================
    if (compacted) {
        unsigned c = 0;
        for (int j = tid; j < curN; j += 256) c += ((cbits[j] >> 16) < T);
        unsigned off = block_exscan(c, wtot, tid, lane) + (unsigned)cum1;
        for (int j = tid; j < curN; j += 256) {
            unsigned cw  = cbits[j];
            unsigned key = cw >> 16, idx = cw & 0xFFFFu;
            if (key < T)       { ids_s[off] = (int)idx; off++; }
            else if (key == T) {
                unsigned pz = atomicAdd(&ctrl[5], 1u);
                if (pz < TCAP) candI[pz] = idx;
            }
        }
    } else {
        unsigned c = 0;
        for (int j = tid; j < NKV/2; j += 256) {
            unsigned w = keysU[j];
            c += ((w & 0xFFFFu) < T) + ((w >> 16) < T);
        }
        unsigned off = block_exscan(c, wtot, tid, lane);
        for (int j = tid; j < NKV/2; j += 256) {
            unsigned w  = keysU[j];
            unsigned k0 = w & 0xFFFFu, k1 = w >> 16;
            if (k0 < T)       { ids_s[off] = 2*j;   off++; }
            else if (k0 == T) {
                unsigned pz = atomicAdd(&ctrl[5], 1u);
                if (pz < TCAP) candI[pz] = (unsigned)(2*j);
            }
            if (k1 < T)       { ids_s[off] = 2*j+1; off++; }
            else if (k1 == T) {
                unsigned pz = atomicAdd(&ctrl[5], 1u);
                if (pz < TCAP) candI[pz] = (unsigned)(2*j+1);
            }
        }
    }
    __syncthreads();

    // full-precision re-rank of boundary group (order-independent, exact)
    int tcount = (int)min(ctrl[5], (unsigned)TCAP);
    for (int t = tid; t < tcount; t += 256) {
        int idx = (int)candI[t];
        candD[t] = d2bits(q0, q1, q2, sq,
                          k_pos[3*idx+0], k_pos[3*idx+1], k_pos[3*idx+2]);
    }
    __syncthreads();
    for (int t = tid; t < tcount; t += 256) {
        unsigned dt = candD[t], it = candI[t];
        int rank = 0;
        for (int s = 0; s < tcount; s++) {
            unsigned ds = candD[s], is = candI[s];
            rank += (ds < dt) || (ds == dt && is < it);
        }
        if (rank < kneedF) ids_s[cless + rank] = (int)it;
    }
    __syncthreads();

    // ================= attention + residual(=2x) + LayerNorm ===============
    const int w = tid >> 5;

    qs[tid] = q_feat[q*CDIM + tid];
    __syncthreads();

    for (int n = w; n < KSEL; n += 8) {
        const float* kr = k_feat + (size_t)ids_s[n] * CDIM;
        float p = 0.f;
        #pragma unroll
        for (int t = 0; t < 8; t++) p = fmaf(qs[lane + 32*t], kr[lane + 32*t], p);
        #pragma unroll
        for (int o = 16; o; o >>= 1) p += __shfl_xor_sync(0xFFFFFFFFu, p, o);
        if (lane == 0) lg[n] = p * 0.0625f;
    }
    __syncthreads();

    if (w == 0) {
        float v0 = lg[lane];
        float v1 = lg[lane + 32];
        float v2 = lg[lane + 64];
        float v3 = (lane < 4) ? lg[lane + 96] : -INFINITY;
        float m = fmaxf(fmaxf(v0, v1), fmaxf(v2, v3));
        #pragma unroll
        for (int o = 16; o; o >>= 1) m = fmaxf(m, __shfl_xor_sync(0xFFFFFFFFu, m, o));
        float e0 = expf(v0 - m), e1 = expf(v1 - m), e2 = expf(v2 - m);
        float e3 = (lane < 4) ? expf(v3 - m) : 0.f;
        float s = e0 + e1 + e2 + e3;
        #pragma unroll
        for (int o = 16; o; o >>= 1) s += __shfl_xor_sync(0xFFFFFFFFu, s, o);
        float inv = 1.0f / s;
        lg[lane]       = e0 * inv;
        lg[lane + 32]  = e1 * inv;
        lg[lane + 64]  = e2 * inv;
        if (lane < 4) lg[lane + 96] = e3 * inv;
    }
    __syncthreads();

    float a0 = 0.f, a1 = 0.f, a2 = 0.f, a3 = 0.f;
    for (int n = 0; n < KSEL; n += 4) {
        a0 = fmaf(lg[n+0], v_feat[(size_t)ids_s[n+0]*CDIM + tid], a0);
        a1 = fmaf(lg[n+1], v_feat[(size_t)ids_s[n+1]*CDIM + tid], a1);
        a2 = fmaf(lg[n+2], v_feat[(size_t)ids_s[n+2]*CDIM + tid], a2);
        a3 = fmaf(lg[n+3], v_feat[(size_t)ids_s[n+3]*CDIM + tid], a3);
    }
    float y = 2.0f * ((a0 + a1) + (a2 + a3));   // res row == x  ->  y = 2x

    float s = y;
    #pragma unroll
    for (int o = 16; o; o >>= 1) s += __shfl_xor_sync(0xFFFFFFFFu, s, o);
    if (lane == 0) red[w] = s;
    __syncthreads();
    float tot = 0.f;
    #pragma unroll
    for (int i = 0; i < 8; i++) tot += red[i];
    float mean = tot * (1.0f / CDIM);
    float d = y - mean;
    float s2 = d * d;
    __syncthreads();
    #pragma unroll
    for (int o = 16; o; o >>= 1) s2 += __shfl_xor_sync(0xFFFFFFFFu, s2, o);
    if (lane == 0) red[w] = s2;
    __syncthreads();
    float tot2 = 0.f;
    #pragma unroll
    for (int i = 0; i < 8; i++) tot2 += red[i];
    float var = tot2 * (1.0f / CDIM);

    out[q*CDIM + tid] = d * rsqrtf(var + 1e-5f) * gamma[tid] + beta[tid];
}

// ---------------------------------------------------------------------------
extern "C" void kernel_launch(void* const* d_in, const int* in_sizes, int n_in,
                              void* d_out, int out_size)
{
    const float* q_feat = (const float*)d_in[1];
    const float* k_feat = (const float*)d_in[2];
    const float* v_feat = (const float*)d_in[3];
    const float* q_pos  = (const float*)d_in[4];
    const float* k_pos  = (const float*)d_in[5];
    const float* gamma  = (const float*)d_in[6];
    const float* beta   = (const float*)d_in[7];
    float* out = (float*)d_out;

    size_t smem = (size_t)(NKV/2 + NBIN*256 + 16 + 8 + CCAP + TCAP + TCAP + 8
                           + 128 /*ids*/ + CDIM /*qs*/ + 128 /*lg*/ + 8 /*red*/)
                  * sizeof(unsigned);
    cudaFuncSetAttribute(fused_kernel,
                         cudaFuncAttributeMaxDynamicSharedMemorySize, (int)smem);

    fused_kernel<<<NQ, 256, smem>>>(q_pos, k_pos, q_feat, k_feat, v_feat,
                                    gamma, beta, out);
}